// round 7
// baseline (speedup 1.0000x reference)
#include <cuda_runtime.h>
#include <cuda_fp16.h>
#include <cstdint>

#define NTOK   49
#define NHD    8
#define HDIM   32
#define DMODEL 256
#define NBATCH 4096
#define NWIN   64
#define MROWS  (NBATCH * NTOK)   // 200704

// fp16 scratch. +2048 halves padding: attn loads 64 padded rows per (b,h).
__device__ __half g_q[(size_t)NBATCH * NHD * NTOK * HDIM + 2048];
__device__ __half g_k[(size_t)NBATCH * NHD * NTOK * HDIM + 2048];
__device__ __half g_v[(size_t)NBATCH * NHD * NTOK * HDIM + 2048];
__device__ __half g_x[(size_t)MROWS * DMODEL];
__device__ __half g_w[3 * 256 * 256];           // [mat][n][k] (W transposed)
__device__ float  g_bm[NWIN * NHD * 64 * 68];   // combined mask+bias, 68-f rows

__device__ __forceinline__ void mma16816(float c[4],
                                         uint32_t a0, uint32_t a1, uint32_t a2, uint32_t a3,
                                         uint32_t b0, uint32_t b1) {
    asm volatile(
        "mma.sync.aligned.m16n8k16.row.col.f32.f16.f16.f32 "
        "{%0,%1,%2,%3}, {%4,%5,%6,%7}, {%8,%9}, {%0,%1,%2,%3};"
        : "+f"(c[0]), "+f"(c[1]), "+f"(c[2]), "+f"(c[3])
        : "r"(a0), "r"(a1), "r"(a2), "r"(a3), "r"(b0), "r"(b1));
}

__device__ __forceinline__ void ldsm4(uint32_t r[4], const void* p) {
    uint32_t a = (uint32_t)__cvta_generic_to_shared(p);
    asm volatile("ldmatrix.sync.aligned.m8n8.x4.shared.b16 {%0,%1,%2,%3}, [%4];"
                 : "=r"(r[0]), "=r"(r[1]), "=r"(r[2]), "=r"(r[3]) : "r"(a));
}

__device__ __forceinline__ void ldsm4t(uint32_t r[4], const void* p) {
    uint32_t a = (uint32_t)__cvta_generic_to_shared(p);
    asm volatile("ldmatrix.sync.aligned.m8n8.x4.trans.shared.b16 {%0,%1,%2,%3}, [%4];"
                 : "=r"(r[0]), "=r"(r[1]), "=r"(r[2]), "=r"(r[3]) : "r"(a));
}

__device__ __forceinline__ void cp16(void* s, const void* g) {
    uint32_t sa = (uint32_t)__cvta_generic_to_shared(s);
    asm volatile("cp.async.cg.shared.global [%0], [%1], 16;" :: "r"(sa), "l"(g));
}

// ---------------------------------------------------------------------------
__global__ __launch_bounds__(256) void convert_x(const float* __restrict__ X) {
    size_t t = (size_t)blockIdx.x * 256 + threadIdx.x;
    float4 v = ((const float4*)X)[t];
    __half2* o = (__half2*)(g_x + t * 4);
    o[0] = __floats2half2_rn(v.x, v.y);
    o[1] = __floats2half2_rn(v.z, v.w);
}

__global__ __launch_bounds__(256) void convert_w(const float* __restrict__ wq,
                                                 const float* __restrict__ wk,
                                                 const float* __restrict__ wv) {
    int mat = blockIdx.x, k = blockIdx.y, n = threadIdx.x;
    const float* W = (mat == 0) ? wq : (mat == 1) ? wk : wv;
    g_w[((size_t)mat * 256 + n) * 256 + k] = __float2half_rn(W[k * 256 + n]);
}

// Combined bias+mask: g_bm[w][h][i<64][j<68] (row stride 68 floats = 272B,
// 16B-aligned for cp.async copy in attn).
__global__ __launch_bounds__(256) void combine_bm(const float* __restrict__ mask,
                                                  const float* __restrict__ table) {
    const int w = blockIdx.x, h = blockIdx.y;
    float* dst = g_bm + ((size_t)(w * NHD + h)) * 64 * 68;
    for (int idx = threadIdx.x; idx < 64 * 68; idx += 256) {
        int i = idx / 68, j = idx - i * 68;
        float v;
        if (j >= NTOK)      v = -1e30f;
        else if (i >= NTOK) v = 0.f;
        else {
            int ih = i / 7, iw = i - ih * 7;
            int jh = j / 7, jw = j - jh * 7;
            int r = (ih - jh + 6) * 13 + (iw - jw + 6);
            v = mask[((size_t)w * NTOK + i) * NTOK + j] + table[r * NHD + h];
        }
        dst[idx] = v;
    }
}

// ---------------------------------------------------------------------------
// Kernel A: QKV projection. BM=128, BN=64, BK=32, 4-stage cp.async pipeline.
// Warp tile 32x32 (4m x 2n warps) -> 32 accum floats -> ~85 regs -> 3 CTAs/SM
// (24 warps feeding HMMA). grid (12, 1568), bx fastest for A-tile L2 reuse.
// Stage: A 128x40 halves (10240B) + B 64x40 halves (5120B) = 15360B.
// ---------------------------------------------------------------------------
#define QKV_STAGE  15360
#define QKV_SMEM   (4 * QKV_STAGE)   // 61440

__global__ __launch_bounds__(256, 3) void qkv_kernel(
    const float* __restrict__ bq, const float* __restrict__ bk,
    const float* __restrict__ bv)
{
    extern __shared__ char smc[];

    const int bx = blockIdx.x, by = blockIdx.y;
    const int tid = threadIdx.x;
    const int warp = tid >> 5, lane = tid & 31;
    const int wm = warp & 3, wn = warp >> 2;
    const int g = lane >> 2, tig = lane & 3;

    const int mat   = bx >> 2;               // 0=Q 1=K 2=V
    const int ncol0 = (bx & 3) * 64;         // 64-col slice of weight
    const float* bias = (mat == 0) ? bq : (mat == 1) ? bk : bv;

    const __half* xrow  = g_x + (size_t)by * 128 * 256;
    const __half* wbase = g_w + ((size_t)mat * 256 + ncol0) * 256;

    auto loadStage = [&](int s, int kp) {
        char* base = smc + s * QKV_STAGE;
        const __half* xs = xrow + kp * 32;
        const __half* ws = wbase + kp * 32;
#pragma unroll
        for (int c = tid; c < 512; c += 256) {       // A: 128 rows x 4 chunks
            int r = c >> 2, off = (c & 3) * 8;
            cp16(base + r * 80 + off * 2, xs + (size_t)r * 256 + off);
        }
        {                                            // B: 64 rows x 4 chunks
            int c = tid;                             // 256 chunks, 1/thread
            int r = c >> 2, off = (c & 3) * 8;
            cp16(base + 10240 + r * 80 + off * 2, ws + (size_t)r * 256 + off);
        }
        asm volatile("cp.async.commit_group;" ::: "memory");
    };

    loadStage(0, 0);
    loadStage(1, 1);
    loadStage(2, 2);

    float acc[2][4][4];
#pragma unroll
    for (int mt = 0; mt < 2; mt++)
#pragma unroll
        for (int nt = 0; nt < 4; nt++)
#pragma unroll
            for (int e = 0; e < 4; e++) acc[mt][nt][e] = 0.f;

    const int aRow = wm * 32 + (lane & 15);
    const int aCol = (lane & 16) >> 1;
    const int bRow = wn * 32 + (lane & 7) + ((lane & 16) >> 1);
    const int bCol = lane & 8;

#pragma unroll
    for (int kp = 0; kp < 8; kp++) {
        if (kp <= 5)      asm volatile("cp.async.wait_group 2;" ::: "memory");
        else if (kp == 6) asm volatile("cp.async.wait_group 1;" ::: "memory");
        else              asm volatile("cp.async.wait_group 0;" ::: "memory");
        __syncthreads();

        if (kp < 5) loadStage((kp + 3) & 3, kp + 3);

        const char* A = smc + (kp & 3) * QKV_STAGE;
        const char* B = A + 10240;

#pragma unroll
        for (int ks = 0; ks < 2; ks++) {
            const int kc = ks * 16;
            uint32_t bf0[4], bf1[4];
            ldsm4(bf0, B + bRow * 80 + (kc + bCol) * 2);
            ldsm4(bf1, B + (bRow + 16) * 80 + (kc + bCol) * 2);
#pragma unroll
            for (int mt = 0; mt < 2; mt++) {
                uint32_t a[4];
                ldsm4(a, A + (aRow + mt * 16) * 80 + (kc + aCol) * 2);
                mma16816(acc[mt][0], a[0], a[1], a[2], a[3], bf0[0], bf0[1]);
                mma16816(acc[mt][1], a[0], a[1], a[2], a[3], bf0[2], bf0[3]);
                mma16816(acc[mt][2], a[0], a[1], a[2], a[3], bf1[0], bf1[1]);
                mma16816(acc[mt][3], a[0], a[1], a[2], a[3], bf1[2], bf1[3]);
            }
        }
    }

    __half* outp = (mat == 0) ? g_q : (mat == 1) ? g_k : g_v;
    const float scale = (mat == 0) ? 0.17677669529663687f : 1.0f;
#pragma unroll
    for (int mt = 0; mt < 2; mt++) {
#pragma unroll
        for (int hf = 0; hf < 2; hf++) {
            int m = by * 128 + wm * 32 + mt * 16 + g + hf * 8;
            int b = m / NTOK, n = m - b * NTOK;
#pragma unroll
            for (int nt = 0; nt < 4; nt++) {
                int c = ncol0 + wn * 32 + nt * 8 + 2 * tig;
                int h = c >> 5, d = c & 31;
                float v0 = (acc[mt][nt][hf * 2 + 0] + bias[c]) * scale;
                float v1 = (acc[mt][nt][hf * 2 + 1] + bias[c + 1]) * scale;
                *(__half2*)(outp + ((((size_t)b * NHD + h) * NTOK + n) * HDIM + d)) =
                    __floats2half2_rn(v0, v1);
            }
        }
    }
}

// ---------------------------------------------------------------------------
// Kernel B: windowed attention. One 128-thr CTA per (b, h). Combined bias+mask
// tile (17KB) prefetched to smem via cp.async (L2-resident; hides under the
// DRAM wait for Q/K/V). Post-mma adds are LDS instead of L2.
// ---------------------------------------------------------------------------
__global__ __launch_bounds__(128, 5) void attn_kernel(float* __restrict__ out)
{
    __shared__ alignas(128) char smraw[41984];
    __half (*Qs)[40] = (__half(*)[40])(smraw);            // 64 x 40  [token][d]
    __half (*Ks)[40] = (__half(*)[40])(smraw + 5120);     // 64 x 40
    __half (*Vs)[40] = (__half(*)[40])(smraw + 10240);    // 64 x 40
    __half (*Ps)[72] = (__half(*)[72])(smraw + 15360);    // 64 x 72  [i][j]
    float* bmS = (float*)(smraw + 24576);                 // 64 x 68
    float* Os = (float*)smraw;   // aliases Qs+Ks after PV phase (post-sync)

    const int b = blockIdx.x;
    const int h = blockIdx.y;
    const int w = b & (NWIN - 1);

    const int tid = threadIdx.x;
    const int warp = tid >> 5, lane = tid & 31;
    const int g = lane >> 2, tig = lane & 3;
    const int m0 = warp * 16;

    const size_t base = ((size_t)b * NHD + h) * (NTOK * HDIM);
    const __half* qp = g_q + base;
    const __half* kp = g_k + base;
    const __half* vp = g_v + base;
    const float* bm = g_bm + ((size_t)(w * NHD + h)) * 64 * 68;

#pragma unroll
    for (int c = tid; c < 256; c += 128) {
        int r = c >> 2, off = (c & 3) * 8;
        cp16(&Qs[r][off], qp + r * 32 + off);
    }
#pragma unroll
    for (int c = tid; c < 256; c += 128) {
        int r = c >> 2, off = (c & 3) * 8;
        cp16(&Ks[r][off], kp + r * 32 + off);
    }
#pragma unroll
    for (int c = tid; c < 256; c += 128) {
        int r = c >> 2, off = (c & 3) * 8;
        cp16(&Vs[r][off], vp + r * 32 + off);
    }
    // bm tile: 64 x 68 floats = 1088 16B chunks
    for (int c = tid; c < 1088; c += 128)
        cp16((char*)bmS + c * 16, (const char*)bm + c * 16);
    asm volatile("cp.async.commit_group;" ::: "memory");
    asm volatile("cp.async.wait_group 0;" ::: "memory");
    __syncthreads();

    float sc[8][4];
#pragma unroll
    for (int nt = 0; nt < 8; nt++)
#pragma unroll
        for (int e = 0; e < 4; e++) sc[nt][e] = 0.f;

#pragma unroll
    for (int ks = 0; ks < 2; ks++) {
        const int kc = ks * 16;
        uint32_t a[4];
        ldsm4(a, &Qs[m0 + (lane & 15)][kc + ((lane & 16) >> 1)]);
#pragma unroll
        for (int t = 0; t < 4; t++) {
            uint32_t bk_[4];
            ldsm4(bk_, &Ks[t * 16 + (lane & 7) + ((lane & 16) >> 1)][kc + (lane & 8)]);
            mma16816(sc[2 * t],     a[0], a[1], a[2], a[3], bk_[0], bk_[1]);
            mma16816(sc[2 * t + 1], a[0], a[1], a[2], a[3], bk_[2], bk_[3]);
        }
    }

    const int i0 = m0 + g, i1 = i0 + 8;
#pragma unroll
    for (int nt = 0; nt < 8; nt++) {
        int jc = nt * 8 + 2 * tig;
        float2 b0 = *(const float2*)&bmS[i0 * 68 + jc];
        float2 b1 = *(const float2*)&bmS[i1 * 68 + jc];
        sc[nt][0] += b0.x; sc[nt][1] += b0.y;
        sc[nt][2] += b1.x; sc[nt][3] += b1.y;
    }

    float mx0 = -1e30f, mx1 = -1e30f;
#pragma unroll
    for (int nt = 0; nt < 8; nt++) {
        mx0 = fmaxf(mx0, fmaxf(sc[nt][0], sc[nt][1]));
        mx1 = fmaxf(mx1, fmaxf(sc[nt][2], sc[nt][3]));
    }
    mx0 = fmaxf(mx0, __shfl_xor_sync(0xffffffffu, mx0, 1));
    mx0 = fmaxf(mx0, __shfl_xor_sync(0xffffffffu, mx0, 2));
    mx1 = fmaxf(mx1, __shfl_xor_sync(0xffffffffu, mx1, 1));
    mx1 = fmaxf(mx1, __shfl_xor_sync(0xffffffffu, mx1, 2));

    float s0 = 0.f, s1 = 0.f;
#pragma unroll
    for (int nt = 0; nt < 8; nt++) {
        sc[nt][0] = __expf(sc[nt][0] - mx0); s0 += sc[nt][0];
        sc[nt][1] = __expf(sc[nt][1] - mx0); s0 += sc[nt][1];
        sc[nt][2] = __expf(sc[nt][2] - mx1); s1 += sc[nt][2];
        sc[nt][3] = __expf(sc[nt][3] - mx1); s1 += sc[nt][3];
    }
    s0 += __shfl_xor_sync(0xffffffffu, s0, 1);
    s0 += __shfl_xor_sync(0xffffffffu, s0, 2);
    s1 += __shfl_xor_sync(0xffffffffu, s1, 1);
    s1 += __shfl_xor_sync(0xffffffffu, s1, 2);
    const float r0 = 1.f / s0, r1 = 1.f / s1;

#pragma unroll
    for (int nt = 0; nt < 8; nt++) {
        int jc = nt * 8 + 2 * tig;
        *(__half2*)&Ps[i0][jc] = __floats2half2_rn(sc[nt][0], sc[nt][1]);
        *(__half2*)&Ps[i1][jc] = __floats2half2_rn(sc[nt][2], sc[nt][3]);
    }
    __syncwarp();

    float o[4][4];
#pragma unroll
    for (int nt = 0; nt < 4; nt++)
#pragma unroll
        for (int e = 0; e < 4; e++) o[nt][e] = 0.f;

#pragma unroll
    for (int kt = 0; kt < 4; kt++) {
        const int kc = kt * 16;
        uint32_t a[4];
        ldsm4(a, &Ps[m0 + (lane & 15)][kc + ((lane & 16) >> 1)]);
        uint32_t bv0[4], bv1[4];
        ldsm4t(bv0, &Vs[kc + (lane & 15)][0  + ((lane & 16) >> 1)]);
        ldsm4t(bv1, &Vs[kc + (lane & 15)][16 + ((lane & 16) >> 1)]);
        mma16816(o[0], a[0], a[1], a[2], a[3], bv0[0], bv0[1]);
        mma16816(o[1], a[0], a[1], a[2], a[3], bv0[2], bv0[3]);
        mma16816(o[2], a[0], a[1], a[2], a[3], bv1[0], bv1[1]);
        mma16816(o[3], a[0], a[1], a[2], a[3], bv1[2], bv1[3]);
    }

    __syncthreads();
    float* Osw = Os + warp * 512;
#pragma unroll
    for (int nt = 0; nt < 4; nt++) {
        int d = nt * 8 + 2 * tig;
        *(float2*)&Osw[g * 32 + d]       = make_float2(o[nt][0] * r0, o[nt][1] * r0);
        *(float2*)&Osw[(g + 8) * 32 + d] = make_float2(o[nt][2] * r1, o[nt][3] * r1);
    }
    __syncwarp();
#pragma unroll
    for (int it = lane; it < 128; it += 32) {
        int r = it >> 3, c = (it & 7) * 4;
        int row = m0 + r;
        if (row < NTOK)
            *(float4*)(out + ((size_t)b * NTOK + row) * DMODEL + h * HDIM + c) =
                *(const float4*)&Osw[r * 32 + c];
    }
}

extern "C" void kernel_launch(void* const* d_in, const int* in_sizes, int n_in,
                              void* d_out, int out_size)
{
    (void)in_sizes; (void)n_in; (void)out_size;
    const float* hidden = (const float*)d_in[0];
    const float* amask  = (const float*)d_in[1];
    const float* wq     = (const float*)d_in[2];
    const float* bq     = (const float*)d_in[3];
    const float* wk     = (const float*)d_in[4];
    const float* bk     = (const float*)d_in[5];
    const float* wv     = (const float*)d_in[6];
    const float* bv     = (const float*)d_in[7];
    const float* table  = (const float*)d_in[8];
    float* out = (float*)d_out;

    cudaFuncSetAttribute(qkv_kernel, cudaFuncAttributeMaxDynamicSharedMemorySize,
                         QKV_SMEM);

    convert_x<<<50176, 256>>>(hidden);
    convert_w<<<dim3(3, 256), 256>>>(wq, wk, wv);
    combine_bm<<<dim3(NWIN, NHD), 256>>>(amask, table);
    qkv_kernel<<<dim3(12, 1568), 256, QKV_SMEM>>>(bq, bk, bv);
    attn_kernel<<<dim3(NBATCH, NHD), 128>>>(out);
}

// round 8
// speedup vs baseline: 1.0752x; 1.0752x over previous
#include <cuda_runtime.h>
#include <cuda_fp16.h>
#include <cstdint>

#define NTOK   49
#define NHD    8
#define HDIM   32
#define DMODEL 256
#define NBATCH 4096
#define NWIN   64
#define MROWS  (NBATCH * NTOK)   // 200704

// fp16 scratch. +2048 halves padding: attn loads 64 padded rows per (b,h).
__device__ __half g_q[(size_t)NBATCH * NHD * NTOK * HDIM + 2048];
__device__ __half g_k[(size_t)NBATCH * NHD * NTOK * HDIM + 2048];
__device__ __half g_v[(size_t)NBATCH * NHD * NTOK * HDIM + 2048];
__device__ __half g_x[(size_t)MROWS * DMODEL];
__device__ __half g_w[3 * 256 * 256];           // [mat][n][k] (W transposed)
__device__ float  g_bm[NWIN * NHD * 64 * 68];   // combined mask+bias, 68-f rows

__device__ __forceinline__ void mma16816(float c[4],
                                         uint32_t a0, uint32_t a1, uint32_t a2, uint32_t a3,
                                         uint32_t b0, uint32_t b1) {
    asm volatile(
        "mma.sync.aligned.m16n8k16.row.col.f32.f16.f16.f32 "
        "{%0,%1,%2,%3}, {%4,%5,%6,%7}, {%8,%9}, {%0,%1,%2,%3};"
        : "+f"(c[0]), "+f"(c[1]), "+f"(c[2]), "+f"(c[3])
        : "r"(a0), "r"(a1), "r"(a2), "r"(a3), "r"(b0), "r"(b1));
}

__device__ __forceinline__ void ldsm4(uint32_t r[4], const void* p) {
    uint32_t a = (uint32_t)__cvta_generic_to_shared(p);
    asm volatile("ldmatrix.sync.aligned.m8n8.x4.shared.b16 {%0,%1,%2,%3}, [%4];"
                 : "=r"(r[0]), "=r"(r[1]), "=r"(r[2]), "=r"(r[3]) : "r"(a));
}

__device__ __forceinline__ void ldsm4t(uint32_t r[4], const void* p) {
    uint32_t a = (uint32_t)__cvta_generic_to_shared(p);
    asm volatile("ldmatrix.sync.aligned.m8n8.x4.trans.shared.b16 {%0,%1,%2,%3}, [%4];"
                 : "=r"(r[0]), "=r"(r[1]), "=r"(r[2]), "=r"(r[3]) : "r"(a));
}

__device__ __forceinline__ void cp16(void* s, const void* g) {
    uint32_t sa = (uint32_t)__cvta_generic_to_shared(s);
    asm volatile("cp.async.cg.shared.global [%0], [%1], 16;" :: "r"(sa), "l"(g));
}

// ---------------------------------------------------------------------------
__global__ __launch_bounds__(256) void convert_x(const float* __restrict__ X) {
    size_t t = (size_t)blockIdx.x * 256 + threadIdx.x;
    float4 v = ((const float4*)X)[t];
    __half2* o = (__half2*)(g_x + t * 4);
    o[0] = __floats2half2_rn(v.x, v.y);
    o[1] = __floats2half2_rn(v.z, v.w);
}

__global__ __launch_bounds__(256) void convert_w(const float* __restrict__ wq,
                                                 const float* __restrict__ wk,
                                                 const float* __restrict__ wv) {
    int mat = blockIdx.x, k = blockIdx.y, n = threadIdx.x;
    const float* W = (mat == 0) ? wq : (mat == 1) ? wk : wv;
    g_w[((size_t)mat * 256 + n) * 256 + k] = __float2half_rn(W[k * 256 + n]);
}

// Combined bias+mask: g_bm[w][h][i<64][j<68] (272B rows, 16B-aligned).
__global__ __launch_bounds__(256) void combine_bm(const float* __restrict__ mask,
                                                  const float* __restrict__ table) {
    const int w = blockIdx.x, h = blockIdx.y;
    float* dst = g_bm + ((size_t)(w * NHD + h)) * 64 * 68;
    for (int idx = threadIdx.x; idx < 64 * 68; idx += 256) {
        int i = idx / 68, j = idx - i * 68;
        float v;
        if (j >= NTOK)      v = -1e30f;
        else if (i >= NTOK) v = 0.f;
        else {
            int ih = i / 7, iw = i - ih * 7;
            int jh = j / 7, jw = j - jh * 7;
            int r = (ih - jh + 6) * 13 + (iw - jw + 6);
            v = mask[((size_t)w * NTOK + i) * NTOK + j] + table[r * NHD + h];
        }
        dst[idx] = v;
    }
}

// ---------------------------------------------------------------------------
// Kernel A: QKV projection (round-4 config — empirically best for HMMA path).
// BM=128, BN=128, BK=64, 2-stage cp.async. 72KB smem -> 2 CTAs/SM.
// 8 warps (2m x 4n), warp tile 64x32. grid (6, 1568), x fastest for A reuse.
// ---------------------------------------------------------------------------
#define QKV_SMEM 73728

__global__ __launch_bounds__(256, 2) void qkv_kernel(
    const float* __restrict__ bq, const float* __restrict__ bk,
    const float* __restrict__ bv)
{
    extern __shared__ __half sm[];   // stage s: As at s*18432, Bs at +9216 (halves)

    const int bx = blockIdx.x, by = blockIdx.y;
    const int tid = threadIdx.x;
    const int warp = tid >> 5, lane = tid & 31;
    const int wm = warp & 1, wn = warp >> 1;
    const int g = lane >> 2, tig = lane & 3;

    const int mat   = bx >> 1;
    const int ncol0 = (bx & 1) * 128;
    const float* bias = (mat == 0) ? bq : (mat == 1) ? bk : bv;

    const __half* xrow  = g_x + (size_t)by * 128 * 256;
    const __half* wbase = g_w + ((size_t)mat * 256 + ncol0) * 256;

    auto loadStage = [&](int s, int kp) {
        __half* A = sm + s * 18432;
        __half* B = sm + s * 18432 + 9216;
        const __half* xs = xrow + kp * 64;
        const __half* ws = wbase + kp * 64;
#pragma unroll
        for (int c = tid; c < 1024; c += 256) {
            int r = c >> 3, off = (c & 7) * 8;
            cp16(A + r * 72 + off, xs + (size_t)r * 256 + off);
        }
#pragma unroll
        for (int c = tid; c < 1024; c += 256) {
            int r = c >> 3, off = (c & 7) * 8;
            cp16(B + r * 72 + off, ws + (size_t)r * 256 + off);
        }
        asm volatile("cp.async.commit_group;" ::: "memory");
    };

    loadStage(0, 0);
    loadStage(1, 1);

    float acc[4][4][4];
#pragma unroll
    for (int mt = 0; mt < 4; mt++)
#pragma unroll
        for (int nt = 0; nt < 4; nt++)
#pragma unroll
            for (int e = 0; e < 4; e++) acc[mt][nt][e] = 0.f;

    const int aRow = wm * 64 + (lane & 15);
    const int aCol = (lane & 16) >> 1;
    const int bRow = wn * 32 + (lane & 7) + ((lane & 16) >> 1);
    const int bCol = lane & 8;

#pragma unroll
    for (int kp = 0; kp < 4; kp++) {
        if (kp < 3) asm volatile("cp.async.wait_group 1;" ::: "memory");
        else        asm volatile("cp.async.wait_group 0;" ::: "memory");
        __syncthreads();

        const __half* A = sm + (kp & 1) * 18432;
        const __half* B = sm + (kp & 1) * 18432 + 9216;

#pragma unroll
        for (int ks = 0; ks < 4; ks++) {
            const int kc = ks * 16;
            uint32_t bf0[4], bf1[4];
            ldsm4(bf0, B + bRow * 72 + kc + bCol);
            ldsm4(bf1, B + (bRow + 16) * 72 + kc + bCol);
#pragma unroll
            for (int mt = 0; mt < 4; mt++) {
                uint32_t a[4];
                ldsm4(a, A + (aRow + mt * 16) * 72 + kc + aCol);
                mma16816(acc[mt][0], a[0], a[1], a[2], a[3], bf0[0], bf0[1]);
                mma16816(acc[mt][1], a[0], a[1], a[2], a[3], bf0[2], bf0[3]);
                mma16816(acc[mt][2], a[0], a[1], a[2], a[3], bf1[0], bf1[1]);
                mma16816(acc[mt][3], a[0], a[1], a[2], a[3], bf1[2], bf1[3]);
            }
        }

        if (kp < 2) {
            __syncthreads();
            loadStage(kp & 1, kp + 2);
        }
    }

    __half* outp = (mat == 0) ? g_q : (mat == 1) ? g_k : g_v;
    const float scale = (mat == 0) ? 0.17677669529663687f : 1.0f;
#pragma unroll
    for (int mt = 0; mt < 4; mt++) {
#pragma unroll
        for (int hf = 0; hf < 2; hf++) {
            int m = by * 128 + wm * 64 + mt * 16 + g + hf * 8;
            int b = m / NTOK, n = m - b * NTOK;
#pragma unroll
            for (int nt = 0; nt < 4; nt++) {
                int c = ncol0 + wn * 32 + nt * 8 + 2 * tig;
                int h = c >> 5, d = c & 31;
                float v0 = (acc[mt][nt][hf * 2 + 0] + bias[c]) * scale;
                float v1 = (acc[mt][nt][hf * 2 + 1] + bias[c + 1]) * scale;
                *(__half2*)(outp + ((((size_t)b * NHD + h) * NTOK + n) * HDIM + d)) =
                    __floats2half2_rn(v0, v1);
            }
        }
    }
}

// ---------------------------------------------------------------------------
// Kernel B: windowed attention, TWO windows per CTA sharing one bm tile.
// Windows b0 and b0+2048 have identical w = b&63 -> identical bias+mask.
// 256 thr: warps 0-3 -> window b0, warps 4-7 -> window b0+2048. Each 4-warp
// half runs the proven per-window pipeline on its private Q/K/V/P buffers.
// smem 66560B -> 3 CTAs/SM (24 warps). Halves bm L2 traffic and CTA count.
// ---------------------------------------------------------------------------
#define WINBUF 24576   // per-window: Qs 5120 + Ks 5120 + Vs 5120 + Ps 9216

__global__ __launch_bounds__(256, 3) void attn_kernel(float* __restrict__ out)
{
    __shared__ alignas(128) char smraw[2 * WINBUF + 17408];

    const int b0 = blockIdx.x;          // 0..2047
    const int h  = blockIdx.y;
    const int w  = b0 & (NWIN - 1);

    const int tid = threadIdx.x;
    const int warp = tid >> 5, lane = tid & 31;
    const int half = warp >> 2;          // which window
    const int wl   = warp & 3;           // warp within window
    const int ht   = tid & 127;          // thread within half
    const int g = lane >> 2, tig = lane & 3;
    const int m0 = wl * 16;

    const int b = b0 + half * 2048;

    char* hb = smraw + half * WINBUF;
    __half (*Qs)[40] = (__half(*)[40])(hb);            // 64 x 40 [token][d]
    __half (*Ks)[40] = (__half(*)[40])(hb + 5120);
    __half (*Vs)[40] = (__half(*)[40])(hb + 10240);
    __half (*Ps)[72] = (__half(*)[72])(hb + 15360);    // 64 x 72 [i][j]
    float* bmS = (float*)(smraw + 2 * WINBUF);         // 64 x 68 shared
    float* Os  = (float*)smraw;   // aliases window buffers after PV (post-sync)

    const size_t base = ((size_t)b * NHD + h) * (NTOK * HDIM);
    const __half* qp = g_q + base;
    const __half* kp = g_k + base;
    const __half* vp = g_v + base;
    const float* bm = g_bm + ((size_t)(w * NHD + h)) * 64 * 68;

    // Q/K/V: each half's 128 threads load their window (rows >=49 read padded
    // garbage; finite, masked via bm). bm: all 256 threads.
#pragma unroll
    for (int c = ht; c < 256; c += 128) {
        int r = c >> 2, off = (c & 3) * 8;
        cp16(&Qs[r][off], qp + r * 32 + off);
    }
#pragma unroll
    for (int c = ht; c < 256; c += 128) {
        int r = c >> 2, off = (c & 3) * 8;
        cp16(&Ks[r][off], kp + r * 32 + off);
    }
#pragma unroll
    for (int c = ht; c < 256; c += 128) {
        int r = c >> 2, off = (c & 3) * 8;
        cp16(&Vs[r][off], vp + r * 32 + off);
    }
    for (int c = tid; c < 1088; c += 256)
        cp16((char*)bmS + c * 16, (const char*)bm + c * 16);
    asm volatile("cp.async.commit_group;" ::: "memory");
    asm volatile("cp.async.wait_group 0;" ::: "memory");
    __syncthreads();

    // --- scores = Q @ K^T (64x64) ---
    float sc[8][4];
#pragma unroll
    for (int nt = 0; nt < 8; nt++)
#pragma unroll
        for (int e = 0; e < 4; e++) sc[nt][e] = 0.f;

#pragma unroll
    for (int ks = 0; ks < 2; ks++) {
        const int kc = ks * 16;
        uint32_t a[4];
        ldsm4(a, &Qs[m0 + (lane & 15)][kc + ((lane & 16) >> 1)]);
#pragma unroll
        for (int t = 0; t < 4; t++) {
            uint32_t bk_[4];
            ldsm4(bk_, &Ks[t * 16 + (lane & 7) + ((lane & 16) >> 1)][kc + (lane & 8)]);
            mma16816(sc[2 * t],     a[0], a[1], a[2], a[3], bk_[0], bk_[1]);
            mma16816(sc[2 * t + 1], a[0], a[1], a[2], a[3], bk_[2], bk_[3]);
        }
    }

    const int i0 = m0 + g, i1 = i0 + 8;
#pragma unroll
    for (int nt = 0; nt < 8; nt++) {
        int jc = nt * 8 + 2 * tig;
        float2 v0 = *(const float2*)&bmS[i0 * 68 + jc];
        float2 v1 = *(const float2*)&bmS[i1 * 68 + jc];
        sc[nt][0] += v0.x; sc[nt][1] += v0.y;
        sc[nt][2] += v1.x; sc[nt][3] += v1.y;
    }

    // --- softmax (rows i0, i1; reduce across 4 tig lanes) ---
    float mx0 = -1e30f, mx1 = -1e30f;
#pragma unroll
    for (int nt = 0; nt < 8; nt++) {
        mx0 = fmaxf(mx0, fmaxf(sc[nt][0], sc[nt][1]));
        mx1 = fmaxf(mx1, fmaxf(sc[nt][2], sc[nt][3]));
    }
    mx0 = fmaxf(mx0, __shfl_xor_sync(0xffffffffu, mx0, 1));
    mx0 = fmaxf(mx0, __shfl_xor_sync(0xffffffffu, mx0, 2));
    mx1 = fmaxf(mx1, __shfl_xor_sync(0xffffffffu, mx1, 1));
    mx1 = fmaxf(mx1, __shfl_xor_sync(0xffffffffu, mx1, 2));

    float s0 = 0.f, s1 = 0.f;
#pragma unroll
    for (int nt = 0; nt < 8; nt++) {
        sc[nt][0] = __expf(sc[nt][0] - mx0); s0 += sc[nt][0];
        sc[nt][1] = __expf(sc[nt][1] - mx0); s0 += sc[nt][1];
        sc[nt][2] = __expf(sc[nt][2] - mx1); s1 += sc[nt][2];
        sc[nt][3] = __expf(sc[nt][3] - mx1); s1 += sc[nt][3];
    }
    s0 += __shfl_xor_sync(0xffffffffu, s0, 1);
    s0 += __shfl_xor_sync(0xffffffffu, s0, 2);
    s1 += __shfl_xor_sync(0xffffffffu, s1, 1);
    s1 += __shfl_xor_sync(0xffffffffu, s1, 2);
    const float r0 = 1.f / s0, r1 = 1.f / s1;

#pragma unroll
    for (int nt = 0; nt < 8; nt++) {
        int jc = nt * 8 + 2 * tig;
        *(__half2*)&Ps[i0][jc] = __floats2half2_rn(sc[nt][0], sc[nt][1]);
        *(__half2*)&Ps[i1][jc] = __floats2half2_rn(sc[nt][2], sc[nt][3]);
    }
    __syncwarp();

    // --- ctx = P @ V ---
    float o[4][4];
#pragma unroll
    for (int nt = 0; nt < 4; nt++)
#pragma unroll
        for (int e = 0; e < 4; e++) o[nt][e] = 0.f;

#pragma unroll
    for (int kt = 0; kt < 4; kt++) {
        const int kc = kt * 16;
        uint32_t a[4];
        ldsm4(a, &Ps[m0 + (lane & 15)][kc + ((lane & 16) >> 1)]);
        uint32_t bv0[4], bv1[4];
        ldsm4t(bv0, &Vs[kc + (lane & 15)][0  + ((lane & 16) >> 1)]);
        ldsm4t(bv1, &Vs[kc + (lane & 15)][16 + ((lane & 16) >> 1)]);
        mma16816(o[0], a[0], a[1], a[2], a[3], bv0[0], bv0[1]);
        mma16816(o[1], a[0], a[1], a[2], a[3], bv0[2], bv0[3]);
        mma16816(o[2], a[0], a[1], a[2], a[3], bv1[0], bv1[1]);
        mma16816(o[3], a[0], a[1], a[2], a[3], bv1[2], bv1[3]);
    }

    // --- stage output (aliases window buffers; all PV reads done), write ---
    __syncthreads();
    float* Osw = Os + warp * 512;   // [16][32] per warp, 16KB total
#pragma unroll
    for (int nt = 0; nt < 4; nt++) {
        int d = nt * 8 + 2 * tig;
        *(float2*)&Osw[g * 32 + d]       = make_float2(o[nt][0] * r0, o[nt][1] * r0);
        *(float2*)&Osw[(g + 8) * 32 + d] = make_float2(o[nt][2] * r1, o[nt][3] * r1);
    }
    __syncwarp();
#pragma unroll
    for (int it = lane; it < 128; it += 32) {
        int r = it >> 3, c = (it & 7) * 4;
        int row = m0 + r;
        if (row < NTOK)
            *(float4*)(out + ((size_t)b * NTOK + row) * DMODEL + h * HDIM + c) =
                *(const float4*)&Osw[r * 32 + c];
    }
}

extern "C" void kernel_launch(void* const* d_in, const int* in_sizes, int n_in,
                              void* d_out, int out_size)
{
    (void)in_sizes; (void)n_in; (void)out_size;
    const float* hidden = (const float*)d_in[0];
    const float* amask  = (const float*)d_in[1];
    const float* wq     = (const float*)d_in[2];
    const float* bq     = (const float*)d_in[3];
    const float* wk     = (const float*)d_in[4];
    const float* bk     = (const float*)d_in[5];
    const float* wv     = (const float*)d_in[6];
    const float* bv     = (const float*)d_in[7];
    const float* table  = (const float*)d_in[8];
    float* out = (float*)d_out;

    cudaFuncSetAttribute(qkv_kernel, cudaFuncAttributeMaxDynamicSharedMemorySize,
                         QKV_SMEM);

    convert_x<<<50176, 256>>>(hidden);
    convert_w<<<dim3(3, 256), 256>>>(wq, wk, wv);
    combine_bm<<<dim3(NWIN, NHD), 256>>>(amask, table);
    qkv_kernel<<<dim3(6, 1568), 256, QKV_SMEM>>>(bq, bk, bv);
    attn_kernel<<<dim3(2048, NHD), 256>>>(out);
}

// round 9
// speedup vs baseline: 1.1114x; 1.0336x over previous
#include <cuda_runtime.h>
#include <cuda_fp16.h>
#include <cstdint>

#define NTOK   49
#define NHD    8
#define HDIM   32
#define DMODEL 256
#define NBATCH 4096
#define NWIN   64
#define MROWS  (NBATCH * NTOK)   // 200704

// fp16 scratch. +2048 halves padding: attn loads 64 padded rows per (b,h).
__device__ __half g_q[(size_t)NBATCH * NHD * NTOK * HDIM + 2048];
__device__ __half g_k[(size_t)NBATCH * NHD * NTOK * HDIM + 2048];
__device__ __half g_v[(size_t)NBATCH * NHD * NTOK * HDIM + 2048];
__device__ __half g_x[(size_t)MROWS * DMODEL];
__device__ __half g_w[3 * 256 * 256];           // [mat][n][k] (W transposed)
__device__ float  g_bm[NWIN * NHD * 64 * 68];   // combined mask+bias, 68-f rows

__device__ __forceinline__ void mma16816(float c[4],
                                         uint32_t a0, uint32_t a1, uint32_t a2, uint32_t a3,
                                         uint32_t b0, uint32_t b1) {
    asm volatile(
        "mma.sync.aligned.m16n8k16.row.col.f32.f16.f16.f32 "
        "{%0,%1,%2,%3}, {%4,%5,%6,%7}, {%8,%9}, {%0,%1,%2,%3};"
        : "+f"(c[0]), "+f"(c[1]), "+f"(c[2]), "+f"(c[3])
        : "r"(a0), "r"(a1), "r"(a2), "r"(a3), "r"(b0), "r"(b1));
}

__device__ __forceinline__ void ldsm4(uint32_t r[4], const void* p) {
    uint32_t a = (uint32_t)__cvta_generic_to_shared(p);
    asm volatile("ldmatrix.sync.aligned.m8n8.x4.shared.b16 {%0,%1,%2,%3}, [%4];"
                 : "=r"(r[0]), "=r"(r[1]), "=r"(r[2]), "=r"(r[3]) : "r"(a));
}

__device__ __forceinline__ void ldsm4t(uint32_t r[4], const void* p) {
    uint32_t a = (uint32_t)__cvta_generic_to_shared(p);
    asm volatile("ldmatrix.sync.aligned.m8n8.x4.trans.shared.b16 {%0,%1,%2,%3}, [%4];"
                 : "=r"(r[0]), "=r"(r[1]), "=r"(r[2]), "=r"(r[3]) : "r"(a));
}

__device__ __forceinline__ void cp16(void* s, const void* g) {
    uint32_t sa = (uint32_t)__cvta_generic_to_shared(s);
    asm volatile("cp.async.cg.shared.global [%0], [%1], 16;" :: "r"(sa), "l"(g));
}

__device__ __forceinline__ uint32_t packh2(float x, float y) {
    __half2 h = __floats2half2_rn(x, y);
    return *(uint32_t*)&h;
}

// ---------------------------------------------------------------------------
__global__ __launch_bounds__(256) void convert_x(const float* __restrict__ X) {
    size_t t = (size_t)blockIdx.x * 256 + threadIdx.x;
    float4 v = ((const float4*)X)[t];
    __half2* o = (__half2*)(g_x + t * 4);
    o[0] = __floats2half2_rn(v.x, v.y);
    o[1] = __floats2half2_rn(v.z, v.w);
}

__global__ __launch_bounds__(256) void convert_w(const float* __restrict__ wq,
                                                 const float* __restrict__ wk,
                                                 const float* __restrict__ wv) {
    int mat = blockIdx.x, k = blockIdx.y, n = threadIdx.x;
    const float* W = (mat == 0) ? wq : (mat == 1) ? wk : wv;
    g_w[((size_t)mat * 256 + n) * 256 + k] = __float2half_rn(W[k * 256 + n]);
}

// Combined bias+mask: g_bm[w][h][i<64][j<68] (272B rows, 16B-aligned).
__global__ __launch_bounds__(256) void combine_bm(const float* __restrict__ mask,
                                                  const float* __restrict__ table) {
    const int w = blockIdx.x, h = blockIdx.y;
    float* dst = g_bm + ((size_t)(w * NHD + h)) * 64 * 68;
    for (int idx = threadIdx.x; idx < 64 * 68; idx += 256) {
        int i = idx / 68, j = idx - i * 68;
        float v;
        if (j >= NTOK)      v = -1e30f;
        else if (i >= NTOK) v = 0.f;
        else {
            int ih = i / 7, iw = i - ih * 7;
            int jh = j / 7, jw = j - jh * 7;
            int r = (ih - jh + 6) * 13 + (iw - jw + 6);
            v = mask[((size_t)w * NTOK + i) * NTOK + j] + table[r * NHD + h];
        }
        dst[idx] = v;
    }
}

// ---------------------------------------------------------------------------
// Kernel A: QKV projection (round-4 config — measured optimum for the legacy
// HMMA path; three configs converge to ~262us). BM=128, BN=128, BK=64,
// 2-stage cp.async. 72KB smem -> 2 CTAs/SM. 8 warps (2m x 4n), warp 64x32.
// ---------------------------------------------------------------------------
#define QKV_SMEM 73728

__global__ __launch_bounds__(256, 2) void qkv_kernel(
    const float* __restrict__ bq, const float* __restrict__ bk,
    const float* __restrict__ bv)
{
    extern __shared__ __half sm[];   // stage s: As at s*18432, Bs at +9216 (halves)

    const int bx = blockIdx.x, by = blockIdx.y;
    const int tid = threadIdx.x;
    const int warp = tid >> 5, lane = tid & 31;
    const int wm = warp & 1, wn = warp >> 1;
    const int g = lane >> 2, tig = lane & 3;

    const int mat   = bx >> 1;
    const int ncol0 = (bx & 1) * 128;
    const float* bias = (mat == 0) ? bq : (mat == 1) ? bk : bv;

    const __half* xrow  = g_x + (size_t)by * 128 * 256;
    const __half* wbase = g_w + ((size_t)mat * 256 + ncol0) * 256;

    auto loadStage = [&](int s, int kp) {
        __half* A = sm + s * 18432;
        __half* B = sm + s * 18432 + 9216;
        const __half* xs = xrow + kp * 64;
        const __half* ws = wbase + kp * 64;
#pragma unroll
        for (int c = tid; c < 1024; c += 256) {
            int r = c >> 3, off = (c & 7) * 8;
            cp16(A + r * 72 + off, xs + (size_t)r * 256 + off);
        }
#pragma unroll
        for (int c = tid; c < 1024; c += 256) {
            int r = c >> 3, off = (c & 7) * 8;
            cp16(B + r * 72 + off, ws + (size_t)r * 256 + off);
        }
        asm volatile("cp.async.commit_group;" ::: "memory");
    };

    loadStage(0, 0);
    loadStage(1, 1);

    float acc[4][4][4];
#pragma unroll
    for (int mt = 0; mt < 4; mt++)
#pragma unroll
        for (int nt = 0; nt < 4; nt++)
#pragma unroll
            for (int e = 0; e < 4; e++) acc[mt][nt][e] = 0.f;

    const int aRow = wm * 64 + (lane & 15);
    const int aCol = (lane & 16) >> 1;
    const int bRow = wn * 32 + (lane & 7) + ((lane & 16) >> 1);
    const int bCol = lane & 8;

#pragma unroll
    for (int kp = 0; kp < 4; kp++) {
        if (kp < 3) asm volatile("cp.async.wait_group 1;" ::: "memory");
        else        asm volatile("cp.async.wait_group 0;" ::: "memory");
        __syncthreads();

        const __half* A = sm + (kp & 1) * 18432;
        const __half* B = sm + (kp & 1) * 18432 + 9216;

#pragma unroll
        for (int ks = 0; ks < 4; ks++) {
            const int kc = ks * 16;
            uint32_t bf0[4], bf1[4];
            ldsm4(bf0, B + bRow * 72 + kc + bCol);
            ldsm4(bf1, B + (bRow + 16) * 72 + kc + bCol);
#pragma unroll
            for (int mt = 0; mt < 4; mt++) {
                uint32_t a[4];
                ldsm4(a, A + (aRow + mt * 16) * 72 + kc + aCol);
                mma16816(acc[mt][0], a[0], a[1], a[2], a[3], bf0[0], bf0[1]);
                mma16816(acc[mt][1], a[0], a[1], a[2], a[3], bf0[2], bf0[3]);
                mma16816(acc[mt][2], a[0], a[1], a[2], a[3], bf1[0], bf1[1]);
                mma16816(acc[mt][3], a[0], a[1], a[2], a[3], bf1[2], bf1[3]);
            }
        }

        if (kp < 2) {
            __syncthreads();
            loadStage(kp & 1, kp + 2);
        }
    }

    __half* outp = (mat == 0) ? g_q : (mat == 1) ? g_k : g_v;
    const float scale = (mat == 0) ? 0.17677669529663687f : 1.0f;
#pragma unroll
    for (int mt = 0; mt < 4; mt++) {
#pragma unroll
        for (int hf = 0; hf < 2; hf++) {
            int m = by * 128 + wm * 64 + mt * 16 + g + hf * 8;
            int b = m / NTOK, n = m - b * NTOK;
#pragma unroll
            for (int nt = 0; nt < 4; nt++) {
                int c = ncol0 + wn * 32 + nt * 8 + 2 * tig;
                int h = c >> 5, d = c & 31;
                float v0 = (acc[mt][nt][hf * 2 + 0] + bias[c]) * scale;
                float v1 = (acc[mt][nt][hf * 2 + 1] + bias[c + 1]) * scale;
                *(__half2*)(outp + ((((size_t)b * NHD + h) * NTOK + n) * HDIM + d)) =
                    __floats2half2_rn(v0, v1);
            }
        }
    }
}

// ---------------------------------------------------------------------------
// Kernel B: windowed attention, two windows per CTA sharing one bm tile
// (b0 and b0+2048 have identical w = b&63). P never touches smem: the QK
// accumulator register layout IS the PV A-fragment layout, so P fragments
// are packed in registers (no STS/LDSM/sync for P, no Ps buffer).
// QK/softmax over 7 n-tiles (keys 0..55); PV kt=3 upper half uses the zero
// fragment (keys 56..63 contribute 0). smem/window: Q+K+V = 15360B.
// ---------------------------------------------------------------------------
#define WINBUF 15360   // Qs 5120 + Ks 5120 + Vs 5120

__global__ __launch_bounds__(256, 3) void attn_kernel(float* __restrict__ out)
{
    __shared__ alignas(128) char smraw[2 * WINBUF + 17408];

    const int b0 = blockIdx.x;          // 0..2047
    const int h  = blockIdx.y;
    const int w  = b0 & (NWIN - 1);

    const int tid = threadIdx.x;
    const int warp = tid >> 5, lane = tid & 31;
    const int half = warp >> 2;          // which window
    const int wl   = warp & 3;           // warp within window
    const int ht   = tid & 127;          // thread within half
    const int g = lane >> 2, tig = lane & 3;
    const int m0 = wl * 16;

    const int b = b0 + half * 2048;

    char* hb = smraw + half * WINBUF;
    __half (*Qs)[40] = (__half(*)[40])(hb);            // 64 x 40 [token][d]
    __half (*Ks)[40] = (__half(*)[40])(hb + 5120);
    __half (*Vs)[40] = (__half(*)[40])(hb + 10240);
    float* bmS = (float*)(smraw + 2 * WINBUF);         // 64 x 68 shared
    float* Os  = (float*)smraw;   // aliases window buffers after PV (post-sync)

    const size_t base = ((size_t)b * NHD + h) * (NTOK * HDIM);
    const __half* qp = g_q + base;
    const __half* kp = g_k + base;
    const __half* vp = g_v + base;
    const float* bm = g_bm + ((size_t)(w * NHD + h)) * 64 * 68;

    // Q/K/V: each half's 128 threads load their window (rows >=49 read padded
    // garbage; finite, masked via bm / zero P fragments). bm: all 256 threads.
#pragma unroll
    for (int c = ht; c < 256; c += 128) {
        int r = c >> 2, off = (c & 3) * 8;
        cp16(&Qs[r][off], qp + r * 32 + off);
    }
#pragma unroll
    for (int c = ht; c < 256; c += 128) {
        int r = c >> 2, off = (c & 3) * 8;
        cp16(&Ks[r][off], kp + r * 32 + off);
    }
#pragma unroll
    for (int c = ht; c < 256; c += 128) {
        int r = c >> 2, off = (c & 3) * 8;
        cp16(&Vs[r][off], vp + r * 32 + off);
    }
    for (int c = tid; c < 1088; c += 256)
        cp16((char*)bmS + c * 16, (const char*)bm + c * 16);
    asm volatile("cp.async.commit_group;" ::: "memory");
    asm volatile("cp.async.wait_group 0;" ::: "memory");
    __syncthreads();

    // --- scores = Q @ K^T (64 rows x 56 key cols: 7 n-tiles) ---
    float sc[7][4];
#pragma unroll
    for (int nt = 0; nt < 7; nt++)
#pragma unroll
        for (int e = 0; e < 4; e++) sc[nt][e] = 0.f;

#pragma unroll
    for (int ks = 0; ks < 2; ks++) {
        const int kc = ks * 16;
        uint32_t a[4];
        ldsm4(a, &Qs[m0 + (lane & 15)][kc + ((lane & 16) >> 1)]);
#pragma unroll
        for (int t = 0; t < 4; t++) {
            uint32_t bk_[4];
            ldsm4(bk_, &Ks[t * 16 + (lane & 7) + ((lane & 16) >> 1)][kc + (lane & 8)]);
            mma16816(sc[2 * t], a[0], a[1], a[2], a[3], bk_[0], bk_[1]);
            if (2 * t + 1 < 7)
                mma16816(sc[2 * t + 1], a[0], a[1], a[2], a[3], bk_[2], bk_[3]);
        }
    }

    const int i0 = m0 + g, i1 = i0 + 8;
#pragma unroll
    for (int nt = 0; nt < 7; nt++) {
        int jc = nt * 8 + 2 * tig;
        float2 v0 = *(const float2*)&bmS[i0 * 68 + jc];
        float2 v1 = *(const float2*)&bmS[i1 * 68 + jc];
        sc[nt][0] += v0.x; sc[nt][1] += v0.y;
        sc[nt][2] += v1.x; sc[nt][3] += v1.y;
    }

    // --- softmax (rows i0, i1; reduce across 4 tig lanes) ---
    float mx0 = -1e30f, mx1 = -1e30f;
#pragma unroll
    for (int nt = 0; nt < 7; nt++) {
        mx0 = fmaxf(mx0, fmaxf(sc[nt][0], sc[nt][1]));
        mx1 = fmaxf(mx1, fmaxf(sc[nt][2], sc[nt][3]));
    }
    mx0 = fmaxf(mx0, __shfl_xor_sync(0xffffffffu, mx0, 1));
    mx0 = fmaxf(mx0, __shfl_xor_sync(0xffffffffu, mx0, 2));
    mx1 = fmaxf(mx1, __shfl_xor_sync(0xffffffffu, mx1, 1));
    mx1 = fmaxf(mx1, __shfl_xor_sync(0xffffffffu, mx1, 2));

    float s0 = 0.f, s1 = 0.f;
#pragma unroll
    for (int nt = 0; nt < 7; nt++) {
        sc[nt][0] = __expf(sc[nt][0] - mx0); s0 += sc[nt][0];
        sc[nt][1] = __expf(sc[nt][1] - mx0); s0 += sc[nt][1];
        sc[nt][2] = __expf(sc[nt][2] - mx1); s1 += sc[nt][2];
        sc[nt][3] = __expf(sc[nt][3] - mx1); s1 += sc[nt][3];
    }
    s0 += __shfl_xor_sync(0xffffffffu, s0, 1);
    s0 += __shfl_xor_sync(0xffffffffu, s0, 2);
    s1 += __shfl_xor_sync(0xffffffffu, s1, 1);
    s1 += __shfl_xor_sync(0xffffffffu, s1, 2);
    const float r0 = 1.f / s0, r1 = 1.f / s1;

    // --- pack P fragments in registers (A-operand layout, unnormalized) ---
    uint32_t pa0[4], pa1[4], pa2[4], pa3[4];
#pragma unroll
    for (int kt = 0; kt < 4; kt++) {
        pa0[kt] = packh2(sc[2 * kt][0], sc[2 * kt][1]);
        pa1[kt] = packh2(sc[2 * kt][2], sc[2 * kt][3]);
        if (2 * kt + 1 < 7) {
            pa2[kt] = packh2(sc[2 * kt + 1][0], sc[2 * kt + 1][1]);
            pa3[kt] = packh2(sc[2 * kt + 1][2], sc[2 * kt + 1][3]);
        } else {
            pa2[kt] = 0u;   // keys 56..63: P = 0 (kills padded-V garbage)
            pa3[kt] = 0u;
        }
    }

    // --- ctx = P @ V (A from registers, B via trans-ldsm) ---
    float o[4][4];
#pragma unroll
    for (int nt = 0; nt < 4; nt++)
#pragma unroll
        for (int e = 0; e < 4; e++) o[nt][e] = 0.f;

#pragma unroll
    for (int kt = 0; kt < 4; kt++) {
        const int kc = kt * 16;
        uint32_t bv0[4], bv1[4];
        ldsm4t(bv0, &Vs[kc + (lane & 15)][0  + ((lane & 16) >> 1)]);
        ldsm4t(bv1, &Vs[kc + (lane & 15)][16 + ((lane & 16) >> 1)]);
        mma16816(o[0], pa0[kt], pa1[kt], pa2[kt], pa3[kt], bv0[0], bv0[1]);
        mma16816(o[1], pa0[kt], pa1[kt], pa2[kt], pa3[kt], bv0[2], bv0[3]);
        mma16816(o[2], pa0[kt], pa1[kt], pa2[kt], pa3[kt], bv1[0], bv1[1]);
        mma16816(o[3], pa0[kt], pa1[kt], pa2[kt], pa3[kt], bv1[2], bv1[3]);
    }

    // --- stage output (aliases window buffers; all ldsm reads done), write ---
    __syncthreads();
    float* Osw = Os + warp * 512;   // [16][32] per warp, 16KB total
#pragma unroll
    for (int nt = 0; nt < 4; nt++) {
        int d = nt * 8 + 2 * tig;
        *(float2*)&Osw[g * 32 + d]       = make_float2(o[nt][0] * r0, o[nt][1] * r0);
        *(float2*)&Osw[(g + 8) * 32 + d] = make_float2(o[nt][2] * r1, o[nt][3] * r1);
    }
    __syncwarp();
#pragma unroll
    for (int it = lane; it < 128; it += 32) {
        int r = it >> 3, c = (it & 7) * 4;
        int row = m0 + r;
        if (row < NTOK)
            *(float4*)(out + ((size_t)b * NTOK + row) * DMODEL + h * HDIM + c) =
                *(const float4*)&Osw[r * 32 + c];
    }
}

extern "C" void kernel_launch(void* const* d_in, const int* in_sizes, int n_in,
                              void* d_out, int out_size)
{
    (void)in_sizes; (void)n_in; (void)out_size;
    const float* hidden = (const float*)d_in[0];
    const float* amask  = (const float*)d_in[1];
    const float* wq     = (const float*)d_in[2];
    const float* bq     = (const float*)d_in[3];
    const float* wk     = (const float*)d_in[4];
    const float* bk     = (const float*)d_in[5];
    const float* wv     = (const float*)d_in[6];
    const float* bv     = (const float*)d_in[7];
    const float* table  = (const float*)d_in[8];
    float* out = (float*)d_out;

    cudaFuncSetAttribute(qkv_kernel, cudaFuncAttributeMaxDynamicSharedMemorySize,
                         QKV_SMEM);

    convert_x<<<50176, 256>>>(hidden);
    convert_w<<<dim3(3, 256), 256>>>(wq, wk, wv);
    combine_bm<<<dim3(NWIN, NHD), 256>>>(amask, table);
    qkv_kernel<<<dim3(6, 1568), 256, QKV_SMEM>>>(bq, bk, bv);
    attn_kernel<<<dim3(2048, NHD), 256>>>(out);
}